// round 10
// baseline (speedup 1.0000x reference)
#include <cuda_runtime.h>
#include <math.h>

#define BB 4
#define LL 8192
#define DD 2048
#define BLT (BB * LL)          // 32768 rows
#define CAP (LL / 2)           // 4096
#define NOISE_SCALE 0.1f
#define AUX_W 0.01f
#define CAP_F 0.5f

#define TPB   256
#define NBLK  (BLT / 8)        // 4096 blocks, 1 row/warp
#define NTAIL (BB + 1)         // 4 select rows + 1 aux
#define SEPT  (LL / TPB)       // 32 keys/thread in select

// Scratch (allocations forbidden)
__device__ unsigned g_keys[BLT];
__device__ float    g_part[NBLK];
__device__ unsigned g_done = 0;    // self-resetting per replay
__device__ unsigned g_fin  = 0;    // self-resetting per replay

__device__ __forceinline__ unsigned atom_add_release_gpu(unsigned* p, unsigned v) {
    unsigned old;
    asm volatile("atom.add.release.gpu.global.u32 %0, [%1], %2;"
                 : "=r"(old) : "l"(p), "r"(v) : "memory");
    return old;
}
__device__ __forceinline__ unsigned ld_acquire_gpu(const unsigned* p) {
    unsigned v;
    asm volatile("ld.acquire.gpu.global.u32 %0, [%1];"
                 : "=r"(v) : "l"(p) : "memory");
    return v;
}

__global__ __launch_bounds__(TPB, 6) void fused_kernel(
    const float* __restrict__ x,
    const float* __restrict__ noise,
    const float* __restrict__ w,
    float* __restrict__ out)
{
    __shared__ float4   sw[DD / 4];      // 8 KB router weight
    __shared__ float    s_ws[8];
    __shared__ unsigned s_ticket;
    __shared__ unsigned s_hist[256];
    __shared__ unsigned s_tot[8];
    __shared__ unsigned s_state[2];      // [0]=prefix, [1]=need
    __shared__ unsigned s_cnt;
    __shared__ int      s_eqn;
    __shared__ int      s_eqi[256];
    __shared__ double   s_dbw[8 * BB];

    const int t    = threadIdx.x;
    const int warp = t >> 5;
    const int lane = t & 31;
    const int bid  = blockIdx.x;

    // ============ phase 1: matvec (identical to the 40us standalone) =====
    const float4* w4 = reinterpret_cast<const float4*>(w);
    sw[t]       = w4[t];
    sw[t + 256] = w4[t + 256];
    __syncthreads();

    const int row = bid * 8 + warp;
    const float4* xr = reinterpret_cast<const float4*>(x + (size_t)row * DD);
    float acc = 0.0f;
#pragma unroll
    for (int j = 0; j < 16; j++) {
        const float4 xv = __ldg(&xr[lane + 32 * j]);
        const float4 wv = sw[lane + 32 * j];
        acc = fmaf(xv.x, wv.x, acc);
        acc = fmaf(xv.y, wv.y, acc);
        acc = fmaf(xv.z, wv.z, acc);
        acc = fmaf(xv.w, wv.w, acc);
    }
#pragma unroll
    for (int o = 16; o; o >>= 1) acc += __shfl_down_sync(0xffffffffu, acc, o);

    if (lane == 0) {
        out[BLT + row] = acc;                                // clean logit
        const float ny = fmaf(noise[row], NOISE_SCALE, acc); // noisy logit
        const unsigned nb = __float_as_uint(ny);
        g_keys[row] = nb ^ (((int)nb >> 31) | 0x80000000u);  // monotone map
        s_ws[warp]  = 1.0f / (1.0f + expf(-acc));
    }
    __syncthreads();
    if (t == 0) {
        float s = 0.0f;
#pragma unroll
        for (int i = 0; i < 8; i++) s += s_ws[i];
        g_part[bid] = s;
        // release-ticket: orders all the block's prior stores (syncthreads
        // above makes them visible to this thread) before the increment.
        s_ticket = atom_add_release_gpu(&g_done, 1u);
    }
    __syncthreads();
    const unsigned ticket = s_ticket;
    if (ticket < NBLK - NTAIL) return;     // not a tail block

    // ============ tail handoff: last 5 finishers (no fences) =============
    if (t == 0) {
        while (ld_acquire_gpu(&g_done) != NBLK) __nanosleep(32);
    }
    __syncthreads();
    const int tail = (int)(ticket - (NBLK - NTAIL));   // 0..4

    if (tail == BB) {
        // ---------------- aux loss ----------------
        double v[BB];
#pragma unroll
        for (int bq = 0; bq < BB; bq++) {
            v[bq] = (double)g_part[bq * 1024 + t]
                  + (double)g_part[bq * 1024 + 256 + t]
                  + (double)g_part[bq * 1024 + 512 + t]
                  + (double)g_part[bq * 1024 + 768 + t];
#pragma unroll
            for (int o = 16; o; o >>= 1)
                v[bq] += __shfl_down_sync(0xffffffffu, v[bq], o);
        }
        if (lane == 0)
#pragma unroll
            for (int bq = 0; bq < BB; bq++) s_dbw[warp * BB + bq] = v[bq];
        __syncthreads();
        if (t == 0) {
            double a = 0.0;
#pragma unroll
            for (int bq = 0; bq < BB; bq++) {
                double s = 0.0;
#pragma unroll
                for (int wq = 0; wq < 8; wq++) s += s_dbw[wq * BB + bq];
                const double d = s / (double)LL - (double)CAP_F;
                a += d * d;
            }
            out[2 * BLT] = (float)((double)AUX_W * a / (double)BB);
        }
    } else {
        // ---------------- per-row top-CAP select ----------------
        // Keys streamed via __ldg each pass: pass 0 from L2, passes 1-3 and
        // the mask pass hit this SM's L1 (32KB row fits; no stale lines —
        // this SM never read these addresses before the acquire).
        const int srow = tail;
        const uint4* kr = reinterpret_cast<const uint4*>(g_keys + srow * LL);

        if (t == 0) { s_state[0] = 0u; s_state[1] = CAP; s_cnt = 0u; s_eqn = 0; }

#pragma unroll
        for (int pass = 0; pass < 4; pass++) {
            const int s  = 24 - 8 * pass;
            const int hs = s + 8;
            s_hist[t] = 0u;
            __syncthreads();
            const unsigned prefix = s_state[0];
            const unsigned need   = s_state[1];
#pragma unroll
            for (int q = 0; q < SEPT / 4; q++) {
                const uint4 kv = __ldg(&kr[t * (SEPT / 4) + q]);
                const unsigned ks[4] = { kv.x, kv.y, kv.z, kv.w };
#pragma unroll
                for (int c = 0; c < 4; c++) {
                    if (pass == 0 || (((ks[c] ^ prefix) >> hs) == 0u))
                        atomicAdd(&s_hist[(ks[c] >> s) & 255u], 1u);
                }
            }
            __syncthreads();
            // cooperative suffix scan over 256 bins (8 warps)
            const unsigned h = s_hist[t];
            unsigned v = h;
#pragma unroll
            for (int o = 1; o < 32; o <<= 1) {
                const unsigned u = __shfl_down_sync(0xffffffffu, v, o);
                if (lane + o < 32) v += u;
            }
            if (lane == 0) s_tot[warp] = v;
            __syncthreads();
            unsigned carry = 0;
#pragma unroll
            for (int w2 = 0; w2 < 8; w2++) if (w2 > warp) carry += s_tot[w2];
            const unsigned S = v + carry;
            if (h > 0u && S >= need && (S - h) < need) {
                s_state[0] = prefix | ((unsigned)t << s);
                s_state[1] = need - (S - h);
            }
            __syncthreads();
        }
        const unsigned thr = s_state[0];   // exact CAP-th largest key

        // mask write + strict-greater count + tie collection (L1 hits)
        float4* m4 = reinterpret_cast<float4*>(out + srow * LL);
        int cg = 0;
#pragma unroll
        for (int q = 0; q < SEPT / 4; q++) {
            const uint4 kv = __ldg(&kr[t * (SEPT / 4) + q]);
            const unsigned ks[4] = { kv.x, kv.y, kv.z, kv.w };
            float4 mv;
            mv.x = (ks[0] > thr) ? 1.0f : 0.0f;
            mv.y = (ks[1] > thr) ? 1.0f : 0.0f;
            mv.z = (ks[2] > thr) ? 1.0f : 0.0f;
            mv.w = (ks[3] > thr) ? 1.0f : 0.0f;
            m4[t * (SEPT / 4) + q] = mv;
            cg += (int)mv.x + (int)mv.y + (int)mv.z + (int)mv.w;
#pragma unroll
            for (int c = 0; c < 4; c++) {
                if (ks[c] == thr) {
                    const int p = atomicAdd(&s_eqn, 1);
                    if (p < 256) s_eqi[p] = t * SEPT + q * 4 + c;
                }
            }
        }
        cg = __reduce_add_sync(0xffffffffu, cg);
        if (lane == 0 && cg) atomicAdd(&s_cnt, (unsigned)cg);
        __syncthreads();

        // promote lowest-index ties to fill exactly CAP (jax top_k order)
        if (t == 0) {
            float* m = out + srow * LL;
            int need = CAP - (int)s_cnt;
            const int n = (s_eqn < 256) ? s_eqn : 256;
            for (int sel = 0; sel < need; sel++) {
                int best = 0x7fffffff, bi = -1;
                for (int q = 0; q < n; q++)
                    if (s_eqi[q] >= 0 && s_eqi[q] < best) { best = s_eqi[q]; bi = q; }
                if (bi < 0) break;
                m[best]   = 1.0f;
                s_eqi[bi] = -1;
            }
        }
    }

    // last tail block resets counters for the next graph replay
    __syncthreads();
    if (t == 0) {
        const unsigned f = atomicAdd(&g_fin, 1u);
        if (f == NTAIL - 1) {      // all 5 tail blocks are past the spin
            g_fin  = 0u;
            g_done = 0u;           // ordered before next replay by kernel end
        }
    }
}

// ---------------------------------------------------------------------------
extern "C" void kernel_launch(void* const* d_in, const int* in_sizes, int n_in,
                              void* d_out, int out_size)
{
    const float* x     = (const float*)d_in[0];
    const float* noise = (const float*)d_in[1];
    const float* w     = (const float*)d_in[2];
    float* out = (float*)d_out;   // [mask BL | logits BL | aux 1]
    (void)in_sizes; (void)n_in; (void)out_size;

    fused_kernel<<<NBLK, TPB>>>(x, noise, w, out);
}

// round 11
// speedup vs baseline: 1.0265x; 1.0265x over previous
#include <cuda_runtime.h>
#include <math.h>

#define BB 4
#define LL 8192
#define DD 2048
#define BLT (BB * LL)          // 32768 rows
#define CAP (LL / 2)           // 4096
#define NOISE_SCALE 0.1f
#define AUX_W 0.01f
#define CAP_F 0.5f

#define TPB   256              // matvec block
#define NBLK  (BLT / 8)        // 4096 matvec blocks, 1 row/warp
#define STPB  1024             // select block
#define SEPT  (LL / STPB)      // 8 keys per thread in select

// Scratch (allocations forbidden)
__device__ unsigned g_keys[BLT];     // order-mapped noisy logits
__device__ float    g_part[NBLK];    // per-block sigmoid partials

// ---------------------------------------------------------------------------
// Kernel 1: router matvec — pure HBM stream (proven ~40us, ~80% DRAM).
// ---------------------------------------------------------------------------
__global__ __launch_bounds__(TPB) void matvec_kernel(
    const float* __restrict__ x,
    const float* __restrict__ noise,
    const float* __restrict__ w,
    float* __restrict__ out)
{
    __shared__ float4 sw[DD / 4];     // 8 KB router weight
    __shared__ float  ssig[8];

    const int t = threadIdx.x;
    const float4* w4 = reinterpret_cast<const float4*>(w);
    sw[t]       = w4[t];
    sw[t + 256] = w4[t + 256];
    __syncthreads();

    const int warp = t >> 5;
    const int lane = t & 31;
    const int row  = blockIdx.x * 8 + warp;

    const float4* xr = reinterpret_cast<const float4*>(x + (size_t)row * DD);
    float acc = 0.0f;
#pragma unroll
    for (int j = 0; j < 16; j++) {
        const float4 xv = __ldg(&xr[lane + 32 * j]);
        const float4 wv = sw[lane + 32 * j];
        acc = fmaf(xv.x, wv.x, acc);
        acc = fmaf(xv.y, wv.y, acc);
        acc = fmaf(xv.z, wv.z, acc);
        acc = fmaf(xv.w, wv.w, acc);
    }
#pragma unroll
    for (int o = 16; o; o >>= 1) acc += __shfl_down_sync(0xffffffffu, acc, o);

    if (lane == 0) {
        out[BLT + row] = acc;                                // clean logit
        const float ny = fmaf(noise[row], NOISE_SCALE, acc); // noisy logit
        const unsigned nb = __float_as_uint(ny);
        g_keys[row] = nb ^ (((int)nb >> 31) | 0x80000000u);  // monotone map
        ssig[warp]  = 1.0f / (1.0f + expf(-acc));
    }
    __syncthreads();
    if (t == 0) {
        float s = 0.0f;
#pragma unroll
        for (int i = 0; i < 8; i++) s += ssig[i];
        g_part[blockIdx.x] = s;      // plain store, no init needed
    }
}

// ---------------------------------------------------------------------------
// Kernel 2: blocks 0..3 = per-row top-CAP select (1024 thr, 8 keys/thr,
// register-resident, prefix-filtered byte radix); block 4 = aux loss.
// ---------------------------------------------------------------------------
__global__ __launch_bounds__(STPB) void select_aux_kernel(float* __restrict__ out)
{
    __shared__ unsigned s_hist[256];
    __shared__ unsigned s_tot[8];
    __shared__ unsigned s_state[2];   // [0]=prefix, [1]=need
    __shared__ unsigned s_cnt;
    __shared__ int      s_eqn;
    __shared__ int      s_eqi[256];
    __shared__ double   s_dbw[32 * BB];

    const int t    = threadIdx.x;
    const int warp = t >> 5;
    const int lane = t & 31;
    const int bid  = blockIdx.x;

    if (bid == BB) {
        // ---------------- aux loss (1024 threads, 1 partial each/batch) ---
        double v[BB];
#pragma unroll
        for (int bq = 0; bq < BB; bq++) {
            v[bq] = (double)g_part[bq * 1024 + t];
#pragma unroll
            for (int o = 16; o; o >>= 1)
                v[bq] += __shfl_down_sync(0xffffffffu, v[bq], o);
        }
        if (lane == 0)
#pragma unroll
            for (int bq = 0; bq < BB; bq++) s_dbw[warp * BB + bq] = v[bq];
        __syncthreads();
        if (t == 0) {
            double a = 0.0;
#pragma unroll
            for (int bq = 0; bq < BB; bq++) {
                double s = 0.0;
#pragma unroll
                for (int wq = 0; wq < 32; wq++) s += s_dbw[wq * BB + bq];
                const double d = s / (double)LL - (double)CAP_F;
                a += d * d;
            }
            out[2 * BLT] = (float)((double)AUX_W * a / (double)BB);
        }
        return;
    }

    // ---------------- per-row top-CAP select ----------------
    const int srow = bid;
    unsigned k[SEPT];
    {
        const uint4* kr = reinterpret_cast<const uint4*>(g_keys + srow * LL);
        const uint4 v0 = __ldg(&kr[t * 2 + 0]);
        const uint4 v1 = __ldg(&kr[t * 2 + 1]);
        k[0] = v0.x; k[1] = v0.y; k[2] = v0.z; k[3] = v0.w;
        k[4] = v1.x; k[5] = v1.y; k[6] = v1.z; k[7] = v1.w;
    }
    if (t == 0) { s_state[0] = 0u; s_state[1] = CAP; s_cnt = 0u; s_eqn = 0; }

    // 4-pass byte radix; passes 1-3 prefix-filtered (few participants)
#pragma unroll
    for (int pass = 0; pass < 4; pass++) {
        const int s  = 24 - 8 * pass;
        const int hs = (pass == 0) ? 0 : (s + 8);
        if (t < 256) s_hist[t] = 0u;
        __syncthreads();
        const unsigned prefix = s_state[0];
        const unsigned need   = s_state[1];
#pragma unroll
        for (int j = 0; j < SEPT; j++) {
            if (pass == 0 || (((k[j] ^ prefix) >> hs) == 0u))
                atomicAdd(&s_hist[(k[j] >> s) & 255u], 1u);
        }
        __syncthreads();
        // cooperative suffix scan over 256 bins (threads 0..255 = 8 warps)
        unsigned h = 0, v = 0;
        if (t < 256) { h = s_hist[t]; v = h; }
#pragma unroll
        for (int o = 1; o < 32; o <<= 1) {
            const unsigned u = __shfl_down_sync(0xffffffffu, v, o);
            if (lane + o < 32) v += u;
        }
        if (t < 256 && lane == 0) s_tot[warp] = v;
        __syncthreads();
        if (t < 256) {
            unsigned carry = 0;
#pragma unroll
            for (int w2 = 0; w2 < 8; w2++) if (w2 > warp) carry += s_tot[w2];
            const unsigned S = v + carry;             // suffix incl. own bin
            if (h > 0u && S >= need && (S - h) < need) {
                s_state[0] = prefix | ((unsigned)t << s);
                s_state[1] = need - (S - h);
            }
        }
        __syncthreads();
    }
    const unsigned thr = s_state[0];                  // exact CAP-th largest

    // mask write + strict-greater count + tie collection (from registers)
    float4* m4 = reinterpret_cast<float4*>(out + srow * LL);
    int cg = 0;
#pragma unroll
    for (int q = 0; q < SEPT / 4; q++) {
        float4 mv;
        mv.x = (k[q * 4 + 0] > thr) ? 1.0f : 0.0f;
        mv.y = (k[q * 4 + 1] > thr) ? 1.0f : 0.0f;
        mv.z = (k[q * 4 + 2] > thr) ? 1.0f : 0.0f;
        mv.w = (k[q * 4 + 3] > thr) ? 1.0f : 0.0f;
        m4[t * (SEPT / 4) + q] = mv;
        cg += (int)mv.x + (int)mv.y + (int)mv.z + (int)mv.w;
#pragma unroll
        for (int c = 0; c < 4; c++) {
            if (k[q * 4 + c] == thr) {
                const int p = atomicAdd(&s_eqn, 1);
                if (p < 256) s_eqi[p] = t * SEPT + q * 4 + c;
            }
        }
    }
    cg = __reduce_add_sync(0xffffffffu, cg);
    if (lane == 0 && cg) atomicAdd(&s_cnt, (unsigned)cg);
    __syncthreads();

    // promote lowest-index ties to fill exactly CAP (jax top_k order)
    if (t == 0) {
        float* m = out + srow * LL;
        int need = CAP - (int)s_cnt;
        const int n = (s_eqn < 256) ? s_eqn : 256;
        for (int sel = 0; sel < need; sel++) {
            int best = 0x7fffffff, bi = -1;
            for (int q = 0; q < n; q++)
                if (s_eqi[q] >= 0 && s_eqi[q] < best) { best = s_eqi[q]; bi = q; }
            if (bi < 0) break;
            m[best]   = 1.0f;
            s_eqi[bi] = -1;
        }
    }
}

// ---------------------------------------------------------------------------
extern "C" void kernel_launch(void* const* d_in, const int* in_sizes, int n_in,
                              void* d_out, int out_size)
{
    const float* x     = (const float*)d_in[0];
    const float* noise = (const float*)d_in[1];
    const float* w     = (const float*)d_in[2];
    float* out = (float*)d_out;   // [mask BL | logits BL | aux 1]
    (void)in_sizes; (void)n_in; (void)out_size;

    matvec_kernel<<<NBLK, TPB>>>(x, noise, w, out);
    select_aux_kernel<<<BB + 1, STPB>>>(out);
}

// round 13
// speedup vs baseline: 1.0803x; 1.0524x over previous
#include <cuda_runtime.h>
#include <math.h>

#define BB 4
#define LL 8192
#define DD 2048
#define BLT (BB * LL)          // 32768 rows
#define CAP (LL / 2)           // 4096
#define NOISE_SCALE 0.1f
#define AUX_W 0.01f
#define CAP_F 0.5f

#define TPB  256
#define RPW  2                 // rows per warp
#define RPB  (8 * RPW)         // 16 rows per block
#define NBLK (BLT / RPB)       // 2048 matvec blocks
#define SEPT (LL / TPB)        // 32 keys per thread in select

// Scratch (allocations forbidden)
__device__ unsigned g_keys[BLT];     // order-mapped noisy logits
__device__ float    g_part[NBLK];    // per-block sigmoid partials

// ---------------------------------------------------------------------------
// Kernel 1: router matvec — 2 independent rows per warp to double per-warp
// MLP (32 outstanding LDG.128 vs 16). Pure HBM stream otherwise.
// ---------------------------------------------------------------------------
__global__ __launch_bounds__(TPB) void matvec_kernel(
    const float* __restrict__ x,
    const float* __restrict__ noise,
    const float* __restrict__ w,
    float* __restrict__ out)
{
    __shared__ float4 sw[DD / 4];     // 8 KB router weight
    __shared__ float  ssig[RPB];

    const int t = threadIdx.x;
    const float4* w4 = reinterpret_cast<const float4*>(w);
    sw[t]       = w4[t];
    sw[t + 256] = w4[t + 256];
    __syncthreads();

    const int warp = t >> 5;
    const int lane = t & 31;
    const int row0 = blockIdx.x * RPB + warp * RPW;   // and row0+1

    const float4* xr0 = reinterpret_cast<const float4*>(x + (size_t)row0 * DD);
    const float4* xr1 = reinterpret_cast<const float4*>(x + (size_t)(row0 + 1) * DD);

    float acc0 = 0.0f, acc1 = 0.0f;
#pragma unroll
    for (int j = 0; j < 16; j++) {
        const float4 a  = __ldg(&xr0[lane + 32 * j]);
        const float4 b  = __ldg(&xr1[lane + 32 * j]);
        const float4 wv = sw[lane + 32 * j];
        acc0 = fmaf(a.x, wv.x, acc0);
        acc0 = fmaf(a.y, wv.y, acc0);
        acc0 = fmaf(a.z, wv.z, acc0);
        acc0 = fmaf(a.w, wv.w, acc0);
        acc1 = fmaf(b.x, wv.x, acc1);
        acc1 = fmaf(b.y, wv.y, acc1);
        acc1 = fmaf(b.z, wv.z, acc1);
        acc1 = fmaf(b.w, wv.w, acc1);
    }
#pragma unroll
    for (int o = 16; o; o >>= 1) {
        acc0 += __shfl_down_sync(0xffffffffu, acc0, o);
        acc1 += __shfl_down_sync(0xffffffffu, acc1, o);
    }

    if (lane == 0) {
        // row 0 of the pair
        out[BLT + row0] = acc0;
        const unsigned nb0 = __float_as_uint(fmaf(noise[row0], NOISE_SCALE, acc0));
        g_keys[row0] = nb0 ^ (((int)nb0 >> 31) | 0x80000000u);
        ssig[warp * RPW] = 1.0f / (1.0f + expf(-acc0));
        // row 1 of the pair
        out[BLT + row0 + 1] = acc1;
        const unsigned nb1 = __float_as_uint(fmaf(noise[row0 + 1], NOISE_SCALE, acc1));
        g_keys[row0 + 1] = nb1 ^ (((int)nb1 >> 31) | 0x80000000u);
        ssig[warp * RPW + 1] = 1.0f / (1.0f + expf(-acc1));
    }
    __syncthreads();
    if (t == 0) {
        float s = 0.0f;
#pragma unroll
        for (int i = 0; i < RPB; i++) s += ssig[i];
        g_part[blockIdx.x] = s;      // plain store, no init needed
    }
}

// ---------------------------------------------------------------------------
// Kernel 2 (R6-proven shape): blocks 0..3 = per-row top-CAP select
// (256 thr, 32 register-resident keys/thr, prefix-filtered byte radix);
// block 4 = aux loss.
// ---------------------------------------------------------------------------
__global__ __launch_bounds__(TPB) void select_aux_kernel(float* __restrict__ out)
{
    __shared__ unsigned s_hist[256];
    __shared__ unsigned s_tot[8];
    __shared__ unsigned s_state[2];   // [0]=prefix, [1]=need
    __shared__ unsigned s_cnt;
    __shared__ int      s_eqn;
    __shared__ int      s_eqi[256];
    __shared__ double   s_dbw[8 * BB];

    const int t    = threadIdx.x;
    const int warp = t >> 5;
    const int lane = t & 31;
    const int bid  = blockIdx.x;

    if (bid == BB) {
        // ---------------- aux loss ----------------
        // batch b owns g_part[b*512 .. b*512+511] (2048 blocks / 4 batches)
        double v[BB];
#pragma unroll
        for (int bq = 0; bq < BB; bq++) {
            v[bq] = (double)g_part[bq * 512 + t]
                  + (double)g_part[bq * 512 + 256 + t];
#pragma unroll
            for (int o = 16; o; o >>= 1)
                v[bq] += __shfl_down_sync(0xffffffffu, v[bq], o);
        }
        if (lane == 0)
#pragma unroll
            for (int bq = 0; bq < BB; bq++) s_dbw[warp * BB + bq] = v[bq];
        __syncthreads();
        if (t == 0) {
            double a = 0.0;
#pragma unroll
            for (int bq = 0; bq < BB; bq++) {
                double s = 0.0;
#pragma unroll
                for (int wq = 0; wq < 8; wq++) s += s_dbw[wq * BB + bq];
                const double d = s / (double)LL - (double)CAP_F;
                a += d * d;
            }
            out[2 * BLT] = (float)((double)AUX_W * a / (double)BB);
        }
        return;
    }

    // ---------------- per-row top-CAP select ----------------
    const int srow = bid;
    unsigned k[SEPT];
    {
        const uint4* kr = reinterpret_cast<const uint4*>(g_keys + srow * LL);
#pragma unroll
        for (int q = 0; q < SEPT / 4; q++) {
            const uint4 v = __ldg(&kr[t * (SEPT / 4) + q]);
            k[q * 4 + 0] = v.x; k[q * 4 + 1] = v.y;
            k[q * 4 + 2] = v.z; k[q * 4 + 3] = v.w;
        }
    }
    if (t == 0) { s_state[0] = 0u; s_state[1] = CAP; s_cnt = 0u; s_eqn = 0; }

    // 4-pass byte radix; passes 1-3 prefix-filtered (few participants)
#pragma unroll
    for (int pass = 0; pass < 4; pass++) {
        const int s  = 24 - 8 * pass;
        const int hs = (pass == 0) ? 0 : (s + 8);
        s_hist[t] = 0u;
        __syncthreads();
        const unsigned prefix = s_state[0];
        const unsigned need   = s_state[1];
#pragma unroll
        for (int j = 0; j < SEPT; j++) {
            if (pass == 0 || (((k[j] ^ prefix) >> hs) == 0u))
                atomicAdd(&s_hist[(k[j] >> s) & 255u], 1u);
        }
        __syncthreads();
        // cooperative suffix scan over 256 bins (8 warps of 32)
        const unsigned h = s_hist[t];
        unsigned v = h;
#pragma unroll
        for (int o = 1; o < 32; o <<= 1) {
            const unsigned u = __shfl_down_sync(0xffffffffu, v, o);
            if (lane + o < 32) v += u;
        }
        if (lane == 0) s_tot[warp] = v;
        __syncthreads();
        unsigned carry = 0;
#pragma unroll
        for (int w2 = 0; w2 < 8; w2++) if (w2 > warp) carry += s_tot[w2];
        const unsigned S = v + carry;                 // suffix incl. own bin
        if (h > 0u && S >= need && (S - h) < need) {
            s_state[0] = prefix | ((unsigned)t << s);
            s_state[1] = need - (S - h);
        }
        __syncthreads();
    }
    const unsigned thr = s_state[0];                  // exact CAP-th largest

    // mask write + strict-greater count + tie collection (from registers)
    float4* m4 = reinterpret_cast<float4*>(out + srow * LL);
    int cg = 0;
#pragma unroll
    for (int q = 0; q < SEPT / 4; q++) {
        float4 mv;
        mv.x = (k[q * 4 + 0] > thr) ? 1.0f : 0.0f;
        mv.y = (k[q * 4 + 1] > thr) ? 1.0f : 0.0f;
        mv.z = (k[q * 4 + 2] > thr) ? 1.0f : 0.0f;
        mv.w = (k[q * 4 + 3] > thr) ? 1.0f : 0.0f;
        m4[t * (SEPT / 4) + q] = mv;
        cg += (int)mv.x + (int)mv.y + (int)mv.z + (int)mv.w;
#pragma unroll
        for (int c = 0; c < 4; c++) {
            if (k[q * 4 + c] == thr) {
                const int p = atomicAdd(&s_eqn, 1);
                if (p < 256) s_eqi[p] = t * SEPT + q * 4 + c;
            }
        }
    }
    cg = __reduce_add_sync(0xffffffffu, cg);
    if (lane == 0 && cg) atomicAdd(&s_cnt, (unsigned)cg);
    __syncthreads();

    // promote lowest-index ties to fill exactly CAP (jax top_k order)
    if (t == 0) {
        float* m = out + srow * LL;
        int need = CAP - (int)s_cnt;
        const int n = (s_eqn < 256) ? s_eqn : 256;
        for (int sel = 0; sel < need; sel++) {
            int best = 0x7fffffff, bi = -1;
            for (int q = 0; q < n; q++)
                if (s_eqi[q] >= 0 && s_eqi[q] < best) { best = s_eqi[q]; bi = q; }
            if (bi < 0) break;
            m[best]   = 1.0f;
            s_eqi[bi] = -1;
        }
    }
}

// ---------------------------------------------------------------------------
extern "C" void kernel_launch(void* const* d_in, const int* in_sizes, int n_in,
                              void* d_out, int out_size)
{
    const float* x     = (const float*)d_in[0];
    const float* noise = (const float*)d_in[1];
    const float* w     = (const float*)d_in[2];
    float* out = (float*)d_out;   // [mask BL | logits BL | aux 1]
    (void)in_sizes; (void)n_in; (void)out_size;

    matvec_kernel<<<NBLK, TPB>>>(x, noise, w, out);
    select_aux_kernel<<<BB + 1, TPB>>>(out);
}

// round 14
// speedup vs baseline: 1.1435x; 1.0585x over previous
#include <cuda_runtime.h>
#include <math.h>

#define BB 4
#define LL 8192
#define DD 2048
#define BLT (BB * LL)          // 32768 rows
#define CAP (LL / 2)           // 4096
#define NOISE_SCALE 0.1f
#define AUX_W 0.01f
#define CAP_F 0.5f

#define TPB  256
#define NBLK (BLT / 8)         // 4096 matvec blocks, 1 row/warp
#define SEPT (LL / TPB)        // 32 keys per thread in select

// Scratch (allocations forbidden). g_hist starts zeroed (static init) and is
// re-zeroed by the select kernel after use -> clean state for every replay.
__device__ unsigned g_keys[BLT];        // order-mapped noisy logits
__device__ float    g_part[NBLK];       // per-block sigmoid partials
__device__ unsigned g_hist[BB][256];    // per-batch top-byte histograms

// ---------------------------------------------------------------------------
// Kernel 1: router matvec (proven R6 shape, ~41.5us) + pass-0 histogram
// accumulation via spread global atomics (hidden under the HBM stream).
// ---------------------------------------------------------------------------
__global__ __launch_bounds__(TPB) void matvec_kernel(
    const float* __restrict__ x,
    const float* __restrict__ noise,
    const float* __restrict__ w,
    float* __restrict__ out)
{
    __shared__ float4 sw[DD / 4];     // 8 KB router weight
    __shared__ float  ssig[8];

    const int t = threadIdx.x;
    const float4* w4 = reinterpret_cast<const float4*>(w);
    sw[t]       = w4[t];
    sw[t + 256] = w4[t + 256];
    __syncthreads();

    const int warp = t >> 5;
    const int lane = t & 31;
    const int row  = blockIdx.x * 8 + warp;

    const float4* xr = reinterpret_cast<const float4*>(x + (size_t)row * DD);
    float acc = 0.0f;
#pragma unroll
    for (int j = 0; j < 16; j++) {
        const float4 xv = __ldg(&xr[lane + 32 * j]);
        const float4 wv = sw[lane + 32 * j];
        acc = fmaf(xv.x, wv.x, acc);
        acc = fmaf(xv.y, wv.y, acc);
        acc = fmaf(xv.z, wv.z, acc);
        acc = fmaf(xv.w, wv.w, acc);
    }
#pragma unroll
    for (int o = 16; o; o >>= 1) acc += __shfl_down_sync(0xffffffffu, acc, o);

    if (lane == 0) {
        out[BLT + row] = acc;                                // clean logit
        const float ny = fmaf(noise[row], NOISE_SCALE, acc); // noisy logit
        const unsigned nb = __float_as_uint(ny);
        const unsigned key = nb ^ (((int)nb >> 31) | 0x80000000u);
        g_keys[row] = key;                                   // monotone map
        atomicAdd(&g_hist[row >> 13][key >> 24], 1u);        // pass-0 bin
        ssig[warp] = 1.0f / (1.0f + expf(-acc));
    }
    __syncthreads();
    if (t == 0) {
        float s = 0.0f;
#pragma unroll
        for (int i = 0; i < 8; i++) s += ssig[i];
        g_part[blockIdx.x] = s;      // plain store, no init needed
    }
}

// ---------------------------------------------------------------------------
// Kernel 2: blocks 0..3 = per-row top-CAP select (pass-0 histogram prebuilt
// by the matvec; only filtered passes 1-3 + mask here); block 4 = aux loss.
// ---------------------------------------------------------------------------
__global__ __launch_bounds__(TPB) void select_aux_kernel(float* __restrict__ out)
{
    __shared__ unsigned s_hist[256];
    __shared__ unsigned s_tot[8];
    __shared__ unsigned s_state[2];   // [0]=prefix, [1]=need
    __shared__ unsigned s_cnt;
    __shared__ int      s_eqn;
    __shared__ int      s_eqi[256];
    __shared__ double   s_dbw[8 * BB];

    const int t    = threadIdx.x;
    const int warp = t >> 5;
    const int lane = t & 31;
    const int bid  = blockIdx.x;

    if (bid == BB) {
        // ---------------- aux loss ----------------
        double v[BB];
#pragma unroll
        for (int bq = 0; bq < BB; bq++) {
            v[bq] = (double)g_part[bq * 1024 + t]
                  + (double)g_part[bq * 1024 + 256 + t]
                  + (double)g_part[bq * 1024 + 512 + t]
                  + (double)g_part[bq * 1024 + 768 + t];
#pragma unroll
            for (int o = 16; o; o >>= 1)
                v[bq] += __shfl_down_sync(0xffffffffu, v[bq], o);
        }
        if (lane == 0)
#pragma unroll
            for (int bq = 0; bq < BB; bq++) s_dbw[warp * BB + bq] = v[bq];
        __syncthreads();
        if (t == 0) {
            double a = 0.0;
#pragma unroll
            for (int bq = 0; bq < BB; bq++) {
                double s = 0.0;
#pragma unroll
                for (int wq = 0; wq < 8; wq++) s += s_dbw[wq * BB + bq];
                const double d = s / (double)LL - (double)CAP_F;
                a += d * d;
            }
            out[2 * BLT] = (float)((double)AUX_W * a / (double)BB);
        }
        return;
    }

    // ---------------- per-row top-CAP select ----------------
    const int srow = bid;
    unsigned k[SEPT];
    {
        const uint4* kr = reinterpret_cast<const uint4*>(g_keys + srow * LL);
#pragma unroll
        for (int q = 0; q < SEPT / 4; q++) {
            const uint4 v = __ldg(&kr[t * (SEPT / 4) + q]);
            k[q * 4 + 0] = v.x; k[q * 4 + 1] = v.y;
            k[q * 4 + 2] = v.z; k[q * 4 + 3] = v.w;
        }
    }

    // ---- pass 0: histogram prebuilt by matvec; read, then zero for replay
    const unsigned h0 = g_hist[srow][t];
    g_hist[srow][t] = 0u;              // reset for next graph replay
    if (t == 0) { s_cnt = 0u; s_eqn = 0; }
    {
        unsigned v = h0;
#pragma unroll
        for (int o = 1; o < 32; o <<= 1) {
            const unsigned u = __shfl_down_sync(0xffffffffu, v, o);
            if (lane + o < 32) v += u;
        }
        if (lane == 0) s_tot[warp] = v;
        __syncthreads();
        unsigned carry = 0;
#pragma unroll
        for (int w2 = 0; w2 < 8; w2++) if (w2 > warp) carry += s_tot[w2];
        const unsigned S = v + carry;                 // suffix incl. own bin
        if (h0 > 0u && S >= (unsigned)CAP && (S - h0) < (unsigned)CAP) {
            s_state[0] = (unsigned)t << 24;
            s_state[1] = (unsigned)CAP - (S - h0);
        }
        __syncthreads();
    }

    // ---- passes 1-3: prefix-filtered (few participants) ----
#pragma unroll
    for (int pass = 1; pass < 4; pass++) {
        const int s  = 24 - 8 * pass;
        const int hs = s + 8;
        s_hist[t] = 0u;
        __syncthreads();
        const unsigned prefix = s_state[0];
        const unsigned need   = s_state[1];
#pragma unroll
        for (int j = 0; j < SEPT; j++) {
            if (((k[j] ^ prefix) >> hs) == 0u)
                atomicAdd(&s_hist[(k[j] >> s) & 255u], 1u);
        }
        __syncthreads();
        const unsigned h = s_hist[t];
        unsigned v = h;
#pragma unroll
        for (int o = 1; o < 32; o <<= 1) {
            const unsigned u = __shfl_down_sync(0xffffffffu, v, o);
            if (lane + o < 32) v += u;
        }
        if (lane == 0) s_tot[warp] = v;
        __syncthreads();
        unsigned carry = 0;
#pragma unroll
        for (int w2 = 0; w2 < 8; w2++) if (w2 > warp) carry += s_tot[w2];
        const unsigned S = v + carry;
        if (h > 0u && S >= need && (S - h) < need) {
            s_state[0] = prefix | ((unsigned)t << s);
            s_state[1] = need - (S - h);
        }
        __syncthreads();
    }
    const unsigned thr = s_state[0];                  // exact CAP-th largest

    // mask write + strict-greater count + tie collection (from registers)
    float4* m4 = reinterpret_cast<float4*>(out + srow * LL);
    int cg = 0;
#pragma unroll
    for (int q = 0; q < SEPT / 4; q++) {
        float4 mv;
        mv.x = (k[q * 4 + 0] > thr) ? 1.0f : 0.0f;
        mv.y = (k[q * 4 + 1] > thr) ? 1.0f : 0.0f;
        mv.z = (k[q * 4 + 2] > thr) ? 1.0f : 0.0f;
        mv.w = (k[q * 4 + 3] > thr) ? 1.0f : 0.0f;
        m4[t * (SEPT / 4) + q] = mv;
        cg += (int)mv.x + (int)mv.y + (int)mv.z + (int)mv.w;
#pragma unroll
        for (int c = 0; c < 4; c++) {
            if (k[q * 4 + c] == thr) {
                const int p = atomicAdd(&s_eqn, 1);
                if (p < 256) s_eqi[p] = t * SEPT + q * 4 + c;
            }
        }
    }
    cg = __reduce_add_sync(0xffffffffu, cg);
    if (lane == 0 && cg) atomicAdd(&s_cnt, (unsigned)cg);
    __syncthreads();

    // promote lowest-index ties to fill exactly CAP (jax top_k order)
    if (t == 0) {
        float* m = out + srow * LL;
        int need = CAP - (int)s_cnt;
        const int n = (s_eqn < 256) ? s_eqn : 256;
        for (int sel = 0; sel < need; sel++) {
            int best = 0x7fffffff, bi = -1;
            for (int q = 0; q < n; q++)
                if (s_eqi[q] >= 0 && s_eqi[q] < best) { best = s_eqi[q]; bi = q; }
            if (bi < 0) break;
            m[best]   = 1.0f;
            s_eqi[bi] = -1;
        }
    }
}

// ---------------------------------------------------------------------------
extern "C" void kernel_launch(void* const* d_in, const int* in_sizes, int n_in,
                              void* d_out, int out_size)
{
    const float* x     = (const float*)d_in[0];
    const float* noise = (const float*)d_in[1];
    const float* w     = (const float*)d_in[2];
    float* out = (float*)d_out;   // [mask BL | logits BL | aux 1]
    (void)in_sizes; (void)n_in; (void)out_size;

    matvec_kernel<<<NBLK, TPB>>>(x, noise, w, out);
    select_aux_kernel<<<BB + 1, TPB>>>(out);
}

// round 15
// speedup vs baseline: 1.1498x; 1.0056x over previous
#include <cuda_runtime.h>
#include <math.h>

#define BB 4
#define LL 8192
#define DD 2048
#define BLT (BB * LL)          // 32768 rows
#define CAP (LL / 2)           // 4096
#define NOISE_SCALE 0.1f
#define AUX_W 0.01f
#define CAP_F 0.5f

#define TPB  256
#define NBLK (BLT / 8)         // 4096 matvec blocks, 1 row/warp
#define SEPT (LL / TPB)        // 32 keys per thread in select

// Scratch (allocations forbidden). g_hist starts zeroed (static init) and is
// re-zeroed by the select kernel after use -> clean state for every replay.
__device__ unsigned g_keys[BLT];        // order-mapped noisy logits
__device__ float    g_part[NBLK];       // per-block sigmoid partials
__device__ unsigned g_hist[BB][256];    // per-batch top-byte histograms

// ---------------------------------------------------------------------------
// Kernel 1: router matvec (proven shape, ~41.5us) + pass-0 histogram via
// spread global atomics. Triggers programmatic launch completion per block.
// ---------------------------------------------------------------------------
__global__ __launch_bounds__(TPB) void matvec_kernel(
    const float* __restrict__ x,
    const float* __restrict__ noise,
    const float* __restrict__ w,
    float* __restrict__ out)
{
    __shared__ float4 sw[DD / 4];     // 8 KB router weight
    __shared__ float  ssig[8];

    const int t = threadIdx.x;
    const float4* w4 = reinterpret_cast<const float4*>(w);
    sw[t]       = w4[t];
    sw[t + 256] = w4[t + 256];
    __syncthreads();

    const int warp = t >> 5;
    const int lane = t & 31;
    const int row  = blockIdx.x * 8 + warp;

    const float4* xr = reinterpret_cast<const float4*>(x + (size_t)row * DD);
    float acc = 0.0f;
#pragma unroll
    for (int j = 0; j < 16; j++) {
        const float4 xv = __ldg(&xr[lane + 32 * j]);
        const float4 wv = sw[lane + 32 * j];
        acc = fmaf(xv.x, wv.x, acc);
        acc = fmaf(xv.y, wv.y, acc);
        acc = fmaf(xv.z, wv.z, acc);
        acc = fmaf(xv.w, wv.w, acc);
    }
#pragma unroll
    for (int o = 16; o; o >>= 1) acc += __shfl_down_sync(0xffffffffu, acc, o);

    if (lane == 0) {
        out[BLT + row] = acc;                                // clean logit
        const float ny = fmaf(noise[row], NOISE_SCALE, acc); // noisy logit
        const unsigned nb = __float_as_uint(ny);
        const unsigned key = nb ^ (((int)nb >> 31) | 0x80000000u);
        g_keys[row] = key;                                   // monotone map
        atomicAdd(&g_hist[row >> 13][key >> 24], 1u);        // pass-0 bin
        ssig[warp] = 1.0f / (1.0f + expf(-acc));
    }
    __syncthreads();
    if (t == 0) {
        float s = 0.0f;
#pragma unroll
        for (int i = 0; i < 8; i++) s += ssig[i];
        g_part[blockIdx.x] = s;      // plain store, no init needed
    }
    __syncthreads();
    // all of this block's stores are issued -> allow dependents to launch
    cudaTriggerProgrammaticLaunchCompletion();
}

// ---------------------------------------------------------------------------
// Kernel 2 (PDL secondary): launched with programmatic stream serialization;
// prologue overlaps the matvec tail, then waits for full visibility.
// Blocks 0..3 = per-row top-CAP select; block 4 = aux loss.
// ---------------------------------------------------------------------------
__global__ __launch_bounds__(TPB) void select_aux_kernel(float* __restrict__ out)
{
    __shared__ unsigned s_hist[256];
    __shared__ unsigned s_tot[8];
    __shared__ unsigned s_state[2];   // [0]=prefix, [1]=need
    __shared__ unsigned s_cnt;
    __shared__ int      s_eqn;
    __shared__ int      s_eqi[256];
    __shared__ double   s_dbw[8 * BB];

    const int t    = threadIdx.x;
    const int warp = t >> 5;
    const int lane = t & 31;
    const int bid  = blockIdx.x;

    // wait for the matvec's memory to be visible (PDL dependency)
    cudaGridDependencySynchronize();

    if (bid == BB) {
        // ---------------- aux loss ----------------
        double v[BB];
#pragma unroll
        for (int bq = 0; bq < BB; bq++) {
            v[bq] = (double)g_part[bq * 1024 + t]
                  + (double)g_part[bq * 1024 + 256 + t]
                  + (double)g_part[bq * 1024 + 512 + t]
                  + (double)g_part[bq * 1024 + 768 + t];
#pragma unroll
            for (int o = 16; o; o >>= 1)
                v[bq] += __shfl_down_sync(0xffffffffu, v[bq], o);
        }
        if (lane == 0)
#pragma unroll
            for (int bq = 0; bq < BB; bq++) s_dbw[warp * BB + bq] = v[bq];
        __syncthreads();
        if (t == 0) {
            double a = 0.0;
#pragma unroll
            for (int bq = 0; bq < BB; bq++) {
                double s = 0.0;
#pragma unroll
                for (int wq = 0; wq < 8; wq++) s += s_dbw[wq * BB + bq];
                const double d = s / (double)LL - (double)CAP_F;
                a += d * d;
            }
            out[2 * BLT] = (float)((double)AUX_W * a / (double)BB);
        }
        return;
    }

    // ---------------- per-row top-CAP select ----------------
    const int srow = bid;
    unsigned k[SEPT];
    {
        const uint4* kr = reinterpret_cast<const uint4*>(g_keys + srow * LL);
#pragma unroll
        for (int q = 0; q < SEPT / 4; q++) {
            const uint4 v = __ldg(&kr[t * (SEPT / 4) + q]);
            k[q * 4 + 0] = v.x; k[q * 4 + 1] = v.y;
            k[q * 4 + 2] = v.z; k[q * 4 + 3] = v.w;
        }
    }

    // ---- pass 0: histogram prebuilt by matvec; read, then zero for replay
    const unsigned h0 = g_hist[srow][t];
    g_hist[srow][t] = 0u;              // reset for next graph replay
    if (t == 0) { s_cnt = 0u; s_eqn = 0; }
    {
        unsigned v = h0;
#pragma unroll
        for (int o = 1; o < 32; o <<= 1) {
            const unsigned u = __shfl_down_sync(0xffffffffu, v, o);
            if (lane + o < 32) v += u;
        }
        if (lane == 0) s_tot[warp] = v;
        __syncthreads();
        unsigned carry = 0;
#pragma unroll
        for (int w2 = 0; w2 < 8; w2++) if (w2 > warp) carry += s_tot[w2];
        const unsigned S = v + carry;                 // suffix incl. own bin
        if (h0 > 0u && S >= (unsigned)CAP && (S - h0) < (unsigned)CAP) {
            s_state[0] = (unsigned)t << 24;
            s_state[1] = (unsigned)CAP - (S - h0);
        }
        __syncthreads();
    }

    // ---- passes 1-3: prefix-filtered (few participants) ----
#pragma unroll
    for (int pass = 1; pass < 4; pass++) {
        const int s  = 24 - 8 * pass;
        const int hs = s + 8;
        s_hist[t] = 0u;
        __syncthreads();
        const unsigned prefix = s_state[0];
        const unsigned need   = s_state[1];
#pragma unroll
        for (int j = 0; j < SEPT; j++) {
            if (((k[j] ^ prefix) >> hs) == 0u)
                atomicAdd(&s_hist[(k[j] >> s) & 255u], 1u);
        }
        __syncthreads();
        const unsigned h = s_hist[t];
        unsigned v = h;
#pragma unroll
        for (int o = 1; o < 32; o <<= 1) {
            const unsigned u = __shfl_down_sync(0xffffffffu, v, o);
            if (lane + o < 32) v += u;
        }
        if (lane == 0) s_tot[warp] = v;
        __syncthreads();
        unsigned carry = 0;
#pragma unroll
        for (int w2 = 0; w2 < 8; w2++) if (w2 > warp) carry += s_tot[w2];
        const unsigned S = v + carry;
        if (h > 0u && S >= need && (S - h) < need) {
            s_state[0] = prefix | ((unsigned)t << s);
            s_state[1] = need - (S - h);
        }
        __syncthreads();
    }
    const unsigned thr = s_state[0];                  // exact CAP-th largest

    // mask write + strict-greater count + tie collection (from registers)
    float4* m4 = reinterpret_cast<float4*>(out + srow * LL);
    int cg = 0;
#pragma unroll
    for (int q = 0; q < SEPT / 4; q++) {
        float4 mv;
        mv.x = (k[q * 4 + 0] > thr) ? 1.0f : 0.0f;
        mv.y = (k[q * 4 + 1] > thr) ? 1.0f : 0.0f;
        mv.z = (k[q * 4 + 2] > thr) ? 1.0f : 0.0f;
        mv.w = (k[q * 4 + 3] > thr) ? 1.0f : 0.0f;
        m4[t * (SEPT / 4) + q] = mv;
        cg += (int)mv.x + (int)mv.y + (int)mv.z + (int)mv.w;
#pragma unroll
        for (int c = 0; c < 4; c++) {
            if (k[q * 4 + c] == thr) {
                const int p = atomicAdd(&s_eqn, 1);
                if (p < 256) s_eqi[p] = t * SEPT + q * 4 + c;
            }
        }
    }
    cg = __reduce_add_sync(0xffffffffu, cg);
    if (lane == 0 && cg) atomicAdd(&s_cnt, (unsigned)cg);
    __syncthreads();

    // promote lowest-index ties to fill exactly CAP (jax top_k order)
    if (t == 0) {
        float* m = out + srow * LL;
        int need = CAP - (int)s_cnt;
        const int n = (s_eqn < 256) ? s_eqn : 256;
        for (int sel = 0; sel < need; sel++) {
            int best = 0x7fffffff, bi = -1;
            for (int q = 0; q < n; q++)
                if (s_eqi[q] >= 0 && s_eqi[q] < best) { best = s_eqi[q]; bi = q; }
            if (bi < 0) break;
            m[best]   = 1.0f;
            s_eqi[bi] = -1;
        }
    }
}

// ---------------------------------------------------------------------------
extern "C" void kernel_launch(void* const* d_in, const int* in_sizes, int n_in,
                              void* d_out, int out_size)
{
    const float* x     = (const float*)d_in[0];
    const float* noise = (const float*)d_in[1];
    const float* w     = (const float*)d_in[2];
    float* out = (float*)d_out;   // [mask BL | logits BL | aux 1]
    (void)in_sizes; (void)n_in; (void)out_size;

    matvec_kernel<<<NBLK, TPB>>>(x, noise, w, out);

    // PDL secondary: prologue overlaps the matvec tail.
    cudaLaunchConfig_t cfg = {};
    cfg.gridDim  = dim3(BB + 1, 1, 1);
    cfg.blockDim = dim3(TPB, 1, 1);
    cfg.dynamicSmemBytes = 0;
    cfg.stream = 0;                    // capture stream (legacy default)
    cudaLaunchAttribute attrs[1];
    attrs[0].id = cudaLaunchAttributeProgrammaticStreamSerialization;
    attrs[0].val.programmaticStreamSerializationAllowed = 1;
    cfg.attrs = attrs;
    cfg.numAttrs = 1;
    cudaLaunchKernelEx(&cfg, select_aux_kernel, out);
}